// round 10
// baseline (speedup 1.0000x reference)
#include <cuda_runtime.h>
#include <cuda_bf16.h>
#include <math.h>
#include <cstdint>

#define D_MODEL 1024
#define D_FF    4096
#define N_HEADS 16
#define D_HEAD  64
#define BATCH   2
#define SEQ     2048
#define NROWS   (BATCH*SEQ)   /* 4096 */

// ---------------- scratch (device globals; no allocation allowed) ----------
__device__ __nv_bfloat16 g_hH  [NROWS * D_MODEL];
__device__ __nv_bfloat16 g_hL  [NROWS * D_MODEL];
__device__ __nv_bfloat16 g_h2H [NROWS * D_MODEL];
__device__ __nv_bfloat16 g_h2L [NROWS * D_MODEL];
__device__ __nv_bfloat16 g_atH [NROWS * D_MODEL];
__device__ __nv_bfloat16 g_atL [NROWS * D_MODEL];
__device__ __nv_bfloat16 g_ffH [NROWS * D_FF];
__device__ __nv_bfloat16 g_ffL [NROWS * D_FF];
__device__ __nv_bfloat16 g_BqH [D_MODEL * D_MODEL];
__device__ __nv_bfloat16 g_BqL [D_MODEL * D_MODEL];
__device__ __nv_bfloat16 g_BkH [D_MODEL * D_MODEL];
__device__ __nv_bfloat16 g_BkL [D_MODEL * D_MODEL];
__device__ __nv_bfloat16 g_BvH [D_MODEL * D_MODEL];
__device__ __nv_bfloat16 g_BvL [D_MODEL * D_MODEL];
__device__ __nv_bfloat16 g_BoH [D_MODEL * D_MODEL];
__device__ __nv_bfloat16 g_BoL [D_MODEL * D_MODEL];
__device__ __nv_bfloat16 g_B1H [D_FF * D_MODEL];
__device__ __nv_bfloat16 g_B1L [D_FF * D_MODEL];
__device__ __nv_bfloat16 g_B2H [D_MODEL * D_FF];
__device__ __nv_bfloat16 g_B2L [D_MODEL * D_FF];
__device__ __nv_bfloat16 g_qh [NROWS * D_MODEL];
__device__ __nv_bfloat16 g_ql [NROWS * D_MODEL];
__device__ __nv_bfloat16 g_kh [NROWS * D_MODEL];
__device__ __nv_bfloat16 g_kl [NROWS * D_MODEL];
__device__ __nv_bfloat16 g_vh [NROWS * D_MODEL];
__device__ __nv_bfloat16 g_vl [NROWS * D_MODEL];
__device__ float g_x1 [NROWS * D_MODEL];

// ================= PTX helpers =============================================
__device__ __forceinline__ uint32_t smem_u32(const void* p) {
    uint32_t a;
    asm("{ .reg .u64 t; cvta.to.shared.u64 t, %1; cvt.u32.u64 %0, t; }" : "=r"(a) : "l"(p));
    return a;
}
__device__ __forceinline__ void cp16(uint32_t s, const void* g) {
    asm volatile("cp.async.cg.shared.global [%0], [%1], 16;" :: "r"(s), "l"(g));
}
#define CP_COMMIT() asm volatile("cp.async.commit_group;" ::: "memory")
#define CP_WAIT(n)  asm volatile("cp.async.wait_group %0;" :: "n"(n) : "memory")

#define LDSM4(r, a) \
    asm volatile("ldmatrix.sync.aligned.m8n8.x4.shared.b16 {%0,%1,%2,%3}, [%4];" \
        : "=r"((r)[0]), "=r"((r)[1]), "=r"((r)[2]), "=r"((r)[3]) : "r"(a))
#define LDSM4T(r, a) \
    asm volatile("ldmatrix.sync.aligned.m8n8.x4.trans.shared.b16 {%0,%1,%2,%3}, [%4];" \
        : "=r"((r)[0]), "=r"((r)[1]), "=r"((r)[2]), "=r"((r)[3]) : "r"(a))

#define MMA16816(c, a, b0, b1) \
    asm volatile("mma.sync.aligned.m16n8k16.row.col.f32.bf16.bf16.f32 " \
        "{%0,%1,%2,%3}, {%4,%5,%6,%7}, {%8,%9}, {%0,%1,%2,%3};" \
        : "+f"((c)[0]), "+f"((c)[1]), "+f"((c)[2]), "+f"((c)[3]) \
        : "r"((a)[0]), "r"((a)[1]), "r"((a)[2]), "r"((a)[3]), "r"(b0), "r"(b1))

// -- GEMM tiling: BM=BN=128, BK=32, 4 planes/stage, 2 stages, 8 warps 2x4 ---
#define BM 128
#define BN 128
#define BK 32
#define GRS 80                             /* smem row stride bytes (40 bf16) */
#define GT  (128 * GRS)                    /* one plane tile: 10240 B */
#define GSTAGEB (4 * GT)                   /* Ah,Al,Bh,Bl: 40960 B */
#define SMEM_GEMM_BYTES (2 * GSTAGEB)      /* 81920 B */

__device__ __forceinline__ float gelu_exact(float v) {
    return 0.5f * v * (1.0f + erff(v * 0.70710678118654752f));
}

// ======= HMMA GEMM: C = (Ah+Al)(Bh+Bl)^T via ah*bh + al*bh + ah*bl =========
// 8 warps (2x4), warp tile 64x32; term sequence limits live fragments.
// EPI: 1 +res->fp32, 2 gelu(+bias)->planes, 3 +bias+res->fp32, 4 scale->planes
template<int EPI>
__global__ __launch_bounds__(256, 2) void hmma_gemm(
    const __nv_bfloat16* __restrict__ Ah, const __nv_bfloat16* __restrict__ Al,
    const __nv_bfloat16* __restrict__ Bh, const __nv_bfloat16* __restrict__ Bl,
    const float* __restrict__ bias,
    const float* __restrict__ res,
    float* __restrict__ C,
    __nv_bfloat16* __restrict__ CH,
    __nv_bfloat16* __restrict__ CL,
    float scale,
    int N, int K)
{
    extern __shared__ char smem[];
    const uint32_t sbase = smem_u32(smem);
    const int tid  = threadIdx.x;
    const int wid  = tid >> 5, lane = tid & 31;
    const int wm   = wid >> 2, wn = wid & 3;       // 2 x 4 warps, 64x32 tiles
    const int rowB = blockIdx.y * BM, colB = blockIdx.x * BN;

    const __nv_bfloat16* srcs[4] = {
        Ah + (size_t)rowB * K, Al + (size_t)rowB * K,
        Bh + (size_t)colB * K, Bl + (size_t)colB * K };

    auto load_stage = [&](int s, int kt) {
        const int k0 = kt * BK;
        const uint32_t st = sbase + s * GSTAGEB;
        #pragma unroll
        for (int i = 0; i < 8; i++) {
            const int tile = i >> 1;                  // 0..3 (const per i)
            const int within = ((i & 1) << 8) + tid;  // 0..511
            const int r = within >> 2, seg = within & 3;
            cp16(st + tile * GT + r * GRS + seg * 16,
                 srcs[tile] + (size_t)r * K + k0 + seg * 8);
        }
        CP_COMMIT();
    };

    float acc[4][4][4];
    #pragma unroll
    for (int i = 0; i < 4; i++)
        #pragma unroll
        for (int j = 0; j < 4; j++)
            #pragma unroll
            for (int q = 0; q < 4; q++) acc[i][j][q] = 0.0f;

    const int niter = K / BK;
    load_stage(0, 0);
    load_stage(1, 1);

    for (int t = 0; t < niter; t++) {
        CP_WAIT(1);
        __syncthreads();
        const uint32_t st = sbase + (t & 1) * GSTAGEB;
        const uint32_t sAh = st, sAl = st + GT, sBh = st + 2*GT, sBl = st + 3*GT;

        #pragma unroll
        for (int ks = 0; ks < 2; ks++) {
            const uint32_t aoff = (wm*64 + (lane & 15)) * GRS
                                + (ks*16 + (lane >> 4) * 8) * 2;
            const uint32_t boff = (wn*32 + (lane >> 4) * 8 + (lane & 7)) * GRS
                                + (ks*16 + ((lane >> 3) & 1) * 8) * 2;
            uint32_t ah[4][4], bh[2][4];
            #pragma unroll
            for (int mi = 0; mi < 4; mi++) LDSM4(ah[mi], sAh + aoff + mi*16*GRS);
            #pragma unroll
            for (int nt = 0; nt < 2; nt++) LDSM4(bh[nt], sBh + boff + nt*16*GRS);
            // term hh
            #pragma unroll
            for (int mi = 0; mi < 4; mi++)
                #pragma unroll
                for (int nt = 0; nt < 2; nt++) {
                    MMA16816(acc[mi][nt*2+0], ah[mi], bh[nt][0], bh[nt][1]);
                    MMA16816(acc[mi][nt*2+1], ah[mi], bh[nt][2], bh[nt][3]);
                }
            // term lh (al x bh) — al live only here
            {
                uint32_t al[4][4];
                #pragma unroll
                for (int mi = 0; mi < 4; mi++) LDSM4(al[mi], sAl + aoff + mi*16*GRS);
                #pragma unroll
                for (int mi = 0; mi < 4; mi++)
                    #pragma unroll
                    for (int nt = 0; nt < 2; nt++) {
                        MMA16816(acc[mi][nt*2+0], al[mi], bh[nt][0], bh[nt][1]);
                        MMA16816(acc[mi][nt*2+1], al[mi], bh[nt][2], bh[nt][3]);
                    }
            }
            // term hl (ah x bl) — bl live only here
            {
                uint32_t bl[2][4];
                #pragma unroll
                for (int nt = 0; nt < 2; nt++) LDSM4(bl[nt], sBl + boff + nt*16*GRS);
                #pragma unroll
                for (int mi = 0; mi < 4; mi++)
                    #pragma unroll
                    for (int nt = 0; nt < 2; nt++) {
                        MMA16816(acc[mi][nt*2+0], ah[mi], bl[nt][0], bl[nt][1]);
                        MMA16816(acc[mi][nt*2+1], ah[mi], bl[nt][2], bl[nt][3]);
                    }
            }
        }
        __syncthreads();
        if (t + 2 < niter) load_stage(t & 1, t + 2);
    }

    const int g  = lane >> 2;
    const int tq = lane & 3;
    #pragma unroll
    for (int mi = 0; mi < 4; mi++) {
        #pragma unroll
        for (int half = 0; half < 2; half++) {
            const int gr = rowB + wm*64 + mi*16 + g + half*8;
            #pragma unroll
            for (int ni = 0; ni < 4; ni++) {
                const int gc = colB + wn*32 + ni*8 + tq*2;
                float v0 = acc[mi][ni][half*2+0];
                float v1 = acc[mi][ni][half*2+1];
                if (EPI == 1) {
                    const float2 r2 = *reinterpret_cast<const float2*>(res + (size_t)gr * N + gc);
                    *reinterpret_cast<float2*>(C + (size_t)gr * N + gc) =
                        make_float2(v0 + r2.x, v1 + r2.y);
                } else if (EPI == 3) {
                    const float2 r2 = *reinterpret_cast<const float2*>(res + (size_t)gr * N + gc);
                    *reinterpret_cast<float2*>(C + (size_t)gr * N + gc) =
                        make_float2(v0 + bias[gc] + r2.x, v1 + bias[gc + 1] + r2.y);
                } else {
                    float s0, s1;
                    if (EPI == 2) {
                        s0 = gelu_exact(v0 + bias[gc]);
                        s1 = gelu_exact(v1 + bias[gc + 1]);
                    } else {           // EPI == 4
                        s0 = v0 * scale; s1 = v1 * scale;
                    }
                    __nv_bfloat162 hi2, lo2;
                    hi2.x = __float2bfloat16(s0);
                    hi2.y = __float2bfloat16(s1);
                    lo2.x = __float2bfloat16(s0 - __bfloat162float(hi2.x));
                    lo2.y = __float2bfloat16(s1 - __bfloat162float(hi2.y));
                    *reinterpret_cast<__nv_bfloat162*>(CH + (size_t)gr * N + gc) = hi2;
                    *reinterpret_cast<__nv_bfloat162*>(CL + (size_t)gr * N + gc) = lo2;
                }
            }
        }
    }
}

// ---------------- layernorm -> planes --------------------------------------
__global__ __launch_bounds__(256) void ln_planes(const float* __restrict__ x,
        const float* __restrict__ g, const float* __restrict__ b,
        __nv_bfloat16* __restrict__ H, __nv_bfloat16* __restrict__ L)
{
    __shared__ float red[256];
    const int row = blockIdx.x, t = threadIdx.x;
    const float4 v = reinterpret_cast<const float4*>(x + (size_t)row * D_MODEL)[t];
    red[t] = v.x + v.y + v.z + v.w;
    __syncthreads();
    #pragma unroll
    for (int o = 128; o > 0; o >>= 1) { if (t < o) red[t] += red[t + o]; __syncthreads(); }
    const float mu = red[0] * (1.0f / D_MODEL);
    __syncthreads();
    const float dx = v.x - mu, dy = v.y - mu, dz = v.z - mu, dw = v.w - mu;
    red[t] = dx*dx + dy*dy + dz*dz + dw*dw;
    __syncthreads();
    #pragma unroll
    for (int o = 128; o > 0; o >>= 1) { if (t < o) red[t] += red[t + o]; __syncthreads(); }
    const float rs = rsqrtf(red[0] * (1.0f / D_MODEL) + 1e-5f);
    const float4 gv = reinterpret_cast<const float4*>(g)[t];
    const float4 bv = reinterpret_cast<const float4*>(b)[t];
    float o4[4] = { dx*rs*gv.x + bv.x, dy*rs*gv.y + bv.y, dz*rs*gv.z + bv.z, dw*rs*gv.w + bv.w };
    __nv_bfloat16 h[4], l[4];
    #pragma unroll
    for (int j = 0; j < 4; j++) {
        h[j] = __float2bfloat16(o4[j]);
        l[j] = __float2bfloat16(o4[j] - __bfloat162float(h[j]));
    }
    const size_t base = (size_t)row * D_MODEL + t * 4;
    *reinterpret_cast<uint2*>(H + base) = *reinterpret_cast<uint2*>(h);
    *reinterpret_cast<uint2*>(L + base) = *reinterpret_cast<uint2*>(l);
}

// ---------------- fp32 -> planes converter ---------------------------------
__global__ __launch_bounds__(256) void conv_planes(const float* __restrict__ src,
        __nv_bfloat16* __restrict__ H, __nv_bfloat16* __restrict__ L, int total)
{
    const int i4 = blockIdx.x * 256 + threadIdx.x;
    if (i4 * 4 >= total) return;
    const float4 v = reinterpret_cast<const float4*>(src)[i4];
    float o4[4] = { v.x, v.y, v.z, v.w };
    __nv_bfloat16 h[4], l[4];
    #pragma unroll
    for (int j = 0; j < 4; j++) {
        h[j] = __float2bfloat16(o4[j]);
        l[j] = __float2bfloat16(o4[j] - __bfloat162float(h[j]));
    }
    *reinterpret_cast<uint2*>(H + (size_t)i4 * 4) = *reinterpret_cast<uint2*>(h);
    *reinterpret_cast<uint2*>(L + (size_t)i4 * 4) = *reinterpret_cast<uint2*>(l);
}

// ========== flash attention on tensor cores (BQ=64, TK=64, 4 warps) ========
#define FSTRIDE 144
#define FTILEB  (64 * FSTRIDE)         /* 9216 */
#define FQ_BYTES (2 * FTILEB)          /* 18432 */
#define FKV_BYTES (4 * FTILEB)         /* 36864 */
#define SMEM_FLASH_BYTES (FQ_BYTES + 2 * FKV_BYTES)  /* 92160 */

__global__ __launch_bounds__(128, 2) void flash_mma(
        const __nv_bfloat16* __restrict__ Qh, const __nv_bfloat16* __restrict__ Ql,
        const __nv_bfloat16* __restrict__ Kh, const __nv_bfloat16* __restrict__ Kl,
        const __nv_bfloat16* __restrict__ Vh, const __nv_bfloat16* __restrict__ Vl,
        __nv_bfloat16* __restrict__ outH, __nv_bfloat16* __restrict__ outL)
{
    extern __shared__ char smem[];
    const uint32_t sb = smem_u32(smem);
    const int tid = threadIdx.x;
    const int w = tid >> 5, lane = tid & 31;
    const int bh = blockIdx.y;                       // 0..31
    const size_t base = (size_t)(bh >> 4) * SEQ * D_MODEL + (size_t)(bh & 15) * D_HEAD;
    const int qb = blockIdx.x * 64;

    #pragma unroll
    for (int i = 0; i < 4; i++) {
        const int c = i * 128 + tid;
        const int row = c >> 3, seg = c & 7;
        const size_t goff = base + (size_t)(qb + row) * D_MODEL + seg * 8;
        cp16(sb + 0      + row * FSTRIDE + seg * 16, Qh + goff);
        cp16(sb + FTILEB + row * FSTRIDE + seg * 16, Ql + goff);
    }
    auto load_kv = [&](int buf, int kt) {
        const uint32_t kvb = sb + FQ_BYTES + buf * FKV_BYTES;
        #pragma unroll
        for (int i = 0; i < 4; i++) {
            const int c = i * 128 + tid;
            const int row = c >> 3, seg = c & 7;
            const size_t goff = base + (size_t)(kt + row) * D_MODEL + seg * 8;
            const uint32_t soff = row * FSTRIDE + seg * 16;
            cp16(kvb + 0*FTILEB + soff, Kh + goff);
            cp16(kvb + 1*FTILEB + soff, Kl + goff);
            cp16(kvb + 2*FTILEB + soff, Vh + goff);
            cp16(kvb + 3*FTILEB + soff, Vl + goff);
        }
        CP_COMMIT();
    };
    load_kv(0, 0);

    float m0 = -1e30f, m1 = -1e30f, l0 = 0.0f, l1 = 0.0f;
    float o[8][4];
    #pragma unroll
    for (int j = 0; j < 8; j++)
        #pragma unroll
        for (int q = 0; q < 4; q++) o[j][q] = 0.0f;

    const uint32_t aQrow = (w*16 + (lane & 15)) * FSTRIDE + (lane >> 4) * 16;
    const uint32_t bKrow = ((lane >> 4) * 8 + (lane & 7)) * FSTRIDE + ((lane >> 3) & 1) * 16;
    const uint32_t bVrow = (lane & 15) * FSTRIDE + (lane >> 4) * 16;

    uint32_t qhf[4][4], qlf[4][4];

    for (int ti = 0; ti < SEQ / 64; ti++) {
        CP_WAIT(0);
        __syncthreads();
        if (ti + 1 < SEQ / 64) load_kv((ti + 1) & 1, (ti + 1) * 64);
        if (ti == 0) {
            #pragma unroll
            for (int ks = 0; ks < 4; ks++) {
                LDSM4(qhf[ks], sb + aQrow + ks * 32);
                LDSM4(qlf[ks], sb + FTILEB + aQrow + ks * 32);
            }
        }
        const uint32_t kvb = sb + FQ_BYTES + (ti & 1) * FKV_BYTES;

        // ---- S: term-major passes per ks (kh fragments shared)
        float s[8][4];
        #pragma unroll
        for (int j = 0; j < 8; j++)
            #pragma unroll
            for (int q = 0; q < 4; q++) s[j][q] = 0.0f;
        #pragma unroll
        for (int ks = 0; ks < 4; ks++) {
            uint32_t bkh[4][4];
            #pragma unroll
            for (int nt = 0; nt < 4; nt++)
                LDSM4(bkh[nt], kvb + bKrow + (nt*16) * FSTRIDE + ks * 32);
            #pragma unroll
            for (int nt = 0; nt < 4; nt++) {
                MMA16816(s[nt*2+0], qhf[ks], bkh[nt][0], bkh[nt][1]);
                MMA16816(s[nt*2+1], qhf[ks], bkh[nt][2], bkh[nt][3]);
            }
            #pragma unroll
            for (int nt = 0; nt < 4; nt++) {
                MMA16816(s[nt*2+0], qlf[ks], bkh[nt][0], bkh[nt][1]);
                MMA16816(s[nt*2+1], qlf[ks], bkh[nt][2], bkh[nt][3]);
            }
            uint32_t bkl[4][4];
            #pragma unroll
            for (int nt = 0; nt < 4; nt++)
                LDSM4(bkl[nt], kvb + FTILEB + bKrow + (nt*16) * FSTRIDE + ks * 32);
            #pragma unroll
            for (int nt = 0; nt < 4; nt++) {
                MMA16816(s[nt*2+0], qhf[ks], bkl[nt][0], bkl[nt][1]);
                MMA16816(s[nt*2+1], qhf[ks], bkl[nt][2], bkl[nt][3]);
            }
        }

        float mx0 = -1e30f, mx1 = -1e30f;
        #pragma unroll
        for (int j = 0; j < 8; j++) {
            mx0 = fmaxf(mx0, fmaxf(s[j][0], s[j][1]));
            mx1 = fmaxf(mx1, fmaxf(s[j][2], s[j][3]));
        }
        mx0 = fmaxf(mx0, __shfl_xor_sync(0xffffffffu, mx0, 1));
        mx0 = fmaxf(mx0, __shfl_xor_sync(0xffffffffu, mx0, 2));
        mx1 = fmaxf(mx1, __shfl_xor_sync(0xffffffffu, mx1, 1));
        mx1 = fmaxf(mx1, __shfl_xor_sync(0xffffffffu, mx1, 2));
        const float mn0 = fmaxf(m0, mx0), mn1 = fmaxf(m1, mx1);
        const float corr0 = __expf(m0 - mn0), corr1 = __expf(m1 - mn1);
        m0 = mn0; m1 = mn1;

        float sum0 = 0.0f, sum1 = 0.0f;
        uint32_t aph[16], apl[16];
        #pragma unroll
        for (int j = 0; j < 8; j++) {
            float p0 = __expf(s[j][0] - mn0), p1 = __expf(s[j][1] - mn0);
            float p2 = __expf(s[j][2] - mn1), p3 = __expf(s[j][3] - mn1);
            sum0 += p0 + p1; sum1 += p2 + p3;
            __nv_bfloat16 h0 = __float2bfloat16(p0), h1 = __float2bfloat16(p1);
            __nv_bfloat16 h2 = __float2bfloat16(p2), h3 = __float2bfloat16(p3);
            __nv_bfloat162 hi01 = __halves2bfloat162(h0, h1);
            __nv_bfloat162 hi23 = __halves2bfloat162(h2, h3);
            __nv_bfloat162 lo01 = __halves2bfloat162(
                __float2bfloat16(p0 - __bfloat162float(h0)),
                __float2bfloat16(p1 - __bfloat162float(h1)));
            __nv_bfloat162 lo23 = __halves2bfloat162(
                __float2bfloat16(p2 - __bfloat162float(h2)),
                __float2bfloat16(p3 - __bfloat162float(h3)));
            const int t4 = (j >> 1) * 4 + (j & 1) * 2;
            aph[t4 + 0] = *reinterpret_cast<uint32_t*>(&hi01);
            aph[t4 + 1] = *reinterpret_cast<uint32_t*>(&hi23);
            apl[t4 + 0] = *reinterpret_cast<uint32_t*>(&lo01);
            apl[t4 + 1] = *reinterpret_cast<uint32_t*>(&lo23);
        }
        sum0 += __shfl_xor_sync(0xffffffffu, sum0, 1);
        sum0 += __shfl_xor_sync(0xffffffffu, sum0, 2);
        sum1 += __shfl_xor_sync(0xffffffffu, sum1, 1);
        sum1 += __shfl_xor_sync(0xffffffffu, sum1, 2);
        l0 = l0 * corr0 + sum0;
        l1 = l1 * corr1 + sum1;
        #pragma unroll
        for (int j = 0; j < 8; j++) {
            o[j][0] *= corr0; o[j][1] *= corr0;
            o[j][2] *= corr1; o[j][3] *= corr1;
        }

        // ---- O: term-major passes per t (vh fragments shared)
        #pragma unroll
        for (int t = 0; t < 4; t++) {
            uint32_t bvh[4][4];
            #pragma unroll
            for (int ns = 0; ns < 4; ns++)
                LDSM4T(bvh[ns], kvb + 2*FTILEB + bVrow + (t*16) * FSTRIDE + ns * 32);
            #pragma unroll
            for (int ns = 0; ns < 4; ns++) {
                MMA16816(o[ns*2+0], aph + t*4, bvh[ns][0], bvh[ns][1]);
                MMA16816(o[ns*2+1], aph + t*4, bvh[ns][2], bvh[ns][3]);
            }
            #pragma unroll
            for (int ns = 0; ns < 4; ns++) {
                MMA16816(o[ns*2+0], apl + t*4, bvh[ns][0], bvh[ns][1]);
                MMA16816(o[ns*2+1], apl + t*4, bvh[ns][2], bvh[ns][3]);
            }
            uint32_t bvl[4][4];
            #pragma unroll
            for (int ns = 0; ns < 4; ns++)
                LDSM4T(bvl[ns], kvb + 3*FTILEB + bVrow + (t*16) * FSTRIDE + ns * 32);
            #pragma unroll
            for (int ns = 0; ns < 4; ns++) {
                MMA16816(o[ns*2+0], aph + t*4, bvl[ns][0], bvl[ns][1]);
                MMA16816(o[ns*2+1], aph + t*4, bvl[ns][2], bvl[ns][3]);
            }
        }
    }

    const float inv0 = 1.0f / l0, inv1 = 1.0f / l1;
    const int r0 = qb + w*16 + (lane >> 2);
    const int gr0 = (bh >> 4) * SEQ + r0;
    const int colb = (bh & 15) * D_HEAD + 2 * (lane & 3);
    #pragma unroll
    for (int j = 0; j < 8; j++) {
        const int col = colb + j * 8;
        float v00 = o[j][0] * inv0, v01 = o[j][1] * inv0;
        float v10 = o[j][2] * inv1, v11 = o[j][3] * inv1;
        __nv_bfloat162 h0, l0b, h1, l1b;
        h0.x = __float2bfloat16(v00); h0.y = __float2bfloat16(v01);
        l0b.x = __float2bfloat16(v00 - __bfloat162float(h0.x));
        l0b.y = __float2bfloat16(v01 - __bfloat162float(h0.y));
        h1.x = __float2bfloat16(v10); h1.y = __float2bfloat16(v11);
        l1b.x = __float2bfloat16(v10 - __bfloat162float(h1.x));
        l1b.y = __float2bfloat16(v11 - __bfloat162float(h1.y));
        const size_t b0 = (size_t)gr0 * D_MODEL + col;
        const size_t b1 = (size_t)(gr0 + 8) * D_MODEL + col;
        *reinterpret_cast<__nv_bfloat162*>(outH + b0) = h0;
        *reinterpret_cast<__nv_bfloat162*>(outL + b0) = l0b;
        *reinterpret_cast<__nv_bfloat162*>(outH + b1) = h1;
        *reinterpret_cast<__nv_bfloat162*>(outL + b1) = l1b;
    }
}

// ---------------- launch --------------------------------------------------
extern "C" void kernel_launch(void* const* d_in, const int* in_sizes, int n_in,
                              void* d_out, int out_size)
{
    const float* x    = (const float*)d_in[0];
    const float* wq   = (const float*)d_in[1];
    const float* wk   = (const float*)d_in[2];
    const float* wv   = (const float*)d_in[3];
    const float* wo   = (const float*)d_in[4];
    const float* w1   = (const float*)d_in[5];
    const float* b1   = (const float*)d_in[6];
    const float* w2   = (const float*)d_in[7];
    const float* b2   = (const float*)d_in[8];
    const float* ln1g = (const float*)d_in[9];
    const float* ln1b = (const float*)d_in[10];
    const float* ln2g = (const float*)d_in[11];
    const float* ln2b = (const float*)d_in[12];
    float* out = (float*)d_out;

    __nv_bfloat16 *hH,*hL,*h2H,*h2L,*atH,*atL,*ffH,*ffL;
    __nv_bfloat16 *BqH,*BqL,*BkH,*BkL,*BvH,*BvL,*BoH,*BoL,*B1H,*B1L,*B2H,*B2L;
    __nv_bfloat16 *qh,*ql,*kh,*kl,*vh,*vl;
    float *x1;
    cudaGetSymbolAddress((void**)&hH,  g_hH);   cudaGetSymbolAddress((void**)&hL,  g_hL);
    cudaGetSymbolAddress((void**)&h2H, g_h2H);  cudaGetSymbolAddress((void**)&h2L, g_h2L);
    cudaGetSymbolAddress((void**)&atH, g_atH);  cudaGetSymbolAddress((void**)&atL, g_atL);
    cudaGetSymbolAddress((void**)&ffH, g_ffH);  cudaGetSymbolAddress((void**)&ffL, g_ffL);
    cudaGetSymbolAddress((void**)&BqH, g_BqH);  cudaGetSymbolAddress((void**)&BqL, g_BqL);
    cudaGetSymbolAddress((void**)&BkH, g_BkH);  cudaGetSymbolAddress((void**)&BkL, g_BkL);
    cudaGetSymbolAddress((void**)&BvH, g_BvH);  cudaGetSymbolAddress((void**)&BvL, g_BvL);
    cudaGetSymbolAddress((void**)&BoH, g_BoH);  cudaGetSymbolAddress((void**)&BoL, g_BoL);
    cudaGetSymbolAddress((void**)&B1H, g_B1H);  cudaGetSymbolAddress((void**)&B1L, g_B1L);
    cudaGetSymbolAddress((void**)&B2H, g_B2H);  cudaGetSymbolAddress((void**)&B2L, g_B2L);
    cudaGetSymbolAddress((void**)&qh,  g_qh);   cudaGetSymbolAddress((void**)&ql,  g_ql);
    cudaGetSymbolAddress((void**)&kh,  g_kh);   cudaGetSymbolAddress((void**)&kl,  g_kl);
    cudaGetSymbolAddress((void**)&vh,  g_vh);   cudaGetSymbolAddress((void**)&vl,  g_vl);
    cudaGetSymbolAddress((void**)&x1,  g_x1);

    cudaFuncSetAttribute(hmma_gemm<1>, cudaFuncAttributeMaxDynamicSharedMemorySize, SMEM_GEMM_BYTES);
    cudaFuncSetAttribute(hmma_gemm<2>, cudaFuncAttributeMaxDynamicSharedMemorySize, SMEM_GEMM_BYTES);
    cudaFuncSetAttribute(hmma_gemm<3>, cudaFuncAttributeMaxDynamicSharedMemorySize, SMEM_GEMM_BYTES);
    cudaFuncSetAttribute(hmma_gemm<4>, cudaFuncAttributeMaxDynamicSharedMemorySize, SMEM_GEMM_BYTES);
    cudaFuncSetAttribute(flash_mma,    cudaFuncAttributeMaxDynamicSharedMemorySize, SMEM_FLASH_BYTES);

    const dim3 blkG(256);
    const dim3 blk(256);
    const dim3 gP (D_MODEL/BN, NROWS/BM);    // (8, 32) = 256 CTAs
    const dim3 gF1(D_FF/BN,    NROWS/BM);    // (32, 32) = 1024 CTAs
    const dim3 gAttn(SEQ/64, BATCH*N_HEADS); // (32, 32)

    ln_planes<<<NROWS, blk>>>(x, ln1g, ln1b, hH, hL);                                        // 1
    conv_planes<<<(D_MODEL*D_MODEL/4+255)/256, blk>>>(wq, BqH, BqL, D_MODEL*D_MODEL);        // 2
    conv_planes<<<(D_MODEL*D_MODEL/4+255)/256, blk>>>(wk, BkH, BkL, D_MODEL*D_MODEL);        // 3
    hmma_gemm<4><<<gP, blkG, SMEM_GEMM_BYTES>>>(hH, hL, BqH, BqL, nullptr, nullptr, nullptr,
                                               qh, ql, 0.125f, D_MODEL, D_MODEL);            // 4 <- profiled
    conv_planes<<<(D_MODEL*D_MODEL/4+255)/256, blk>>>(wv, BvH, BvL, D_MODEL*D_MODEL);        // 5
    hmma_gemm<4><<<gP, blkG, SMEM_GEMM_BYTES>>>(hH, hL, BkH, BkL, nullptr, nullptr, nullptr,
                                               kh, kl, 1.0f, D_MODEL, D_MODEL);              // 6
    hmma_gemm<4><<<gP, blkG, SMEM_GEMM_BYTES>>>(hH, hL, BvH, BvL, nullptr, nullptr, nullptr,
                                               vh, vl, 1.0f, D_MODEL, D_MODEL);              // 7
    conv_planes<<<(D_MODEL*D_MODEL/4+255)/256, blk>>>(wo, BoH, BoL, D_MODEL*D_MODEL);        // 8
    conv_planes<<<(D_FF*D_MODEL/4+255)/256,    blk>>>(w1, B1H, B1L, D_FF*D_MODEL);           // 9
    conv_planes<<<(D_MODEL*D_FF/4+255)/256,    blk>>>(w2, B2H, B2L, D_MODEL*D_FF);           // 10
    flash_mma<<<gAttn, dim3(128), SMEM_FLASH_BYTES>>>(qh, ql, kh, kl, vh, vl, atH, atL);     // 11
    hmma_gemm<1><<<gP, blkG, SMEM_GEMM_BYTES>>>(atH, atL, BoH, BoL, nullptr, x, x1,
                                               nullptr, nullptr, 1.0f, D_MODEL, D_MODEL);    // 12
    ln_planes<<<NROWS, blk>>>(x1, ln2g, ln2b, h2H, h2L);                                     // 13
    hmma_gemm<2><<<gF1, blkG, SMEM_GEMM_BYTES>>>(h2H, h2L, B1H, B1L, b1, nullptr, nullptr,
                                               ffH, ffL, 1.0f, D_FF, D_MODEL);               // 14
    hmma_gemm<3><<<gP, blkG, SMEM_GEMM_BYTES>>>(ffH, ffL, B2H, B2L, b2, x1, out,
                                               nullptr, nullptr, 1.0f, D_MODEL, D_FF);       // 15
}

// round 11
// speedup vs baseline: 1.3617x; 1.3617x over previous
#include <cuda_runtime.h>
#include <cuda_fp16.h>
#include <math.h>
#include <cstdint>

#define D_MODEL 1024
#define D_FF    4096
#define N_HEADS 16
#define D_HEAD  64
#define BATCH   2
#define SEQ     2048
#define NROWS   (BATCH*SEQ)   /* 4096 */

// ---------------- scratch (device globals; no allocation allowed) ----------
// A-side operands: (hi, lo) fp16 planes.  B-side operands: single fp16 plane.
__device__ __half g_hH  [NROWS * D_MODEL];
__device__ __half g_hL  [NROWS * D_MODEL];
__device__ __half g_h2H [NROWS * D_MODEL];
__device__ __half g_h2L [NROWS * D_MODEL];
__device__ __half g_atH [NROWS * D_MODEL];
__device__ __half g_atL [NROWS * D_MODEL];
__device__ __half g_ffH [NROWS * D_FF];
__device__ __half g_ffL [NROWS * D_FF];
__device__ __half g_Bq  [D_MODEL * D_MODEL];
__device__ __half g_Bk  [D_MODEL * D_MODEL];
__device__ __half g_Bv  [D_MODEL * D_MODEL];
__device__ __half g_Bo  [D_MODEL * D_MODEL];
__device__ __half g_B1  [D_FF * D_MODEL];
__device__ __half g_B2  [D_MODEL * D_FF];
__device__ __half g_qh [NROWS * D_MODEL];
__device__ __half g_ql [NROWS * D_MODEL];
__device__ __half g_kh [NROWS * D_MODEL];
__device__ __half g_kl [NROWS * D_MODEL];   // written, unused (shared epilogue)
__device__ __half g_vh [NROWS * D_MODEL];
__device__ __half g_vl [NROWS * D_MODEL];   // written, unused
__device__ float g_x1 [NROWS * D_MODEL];

// ================= PTX helpers =============================================
__device__ __forceinline__ uint32_t smem_u32(const void* p) {
    uint32_t a;
    asm("{ .reg .u64 t; cvta.to.shared.u64 t, %1; cvt.u32.u64 %0, t; }" : "=r"(a) : "l"(p));
    return a;
}
__device__ __forceinline__ void cp16(uint32_t s, const void* g) {
    asm volatile("cp.async.cg.shared.global [%0], [%1], 16;" :: "r"(s), "l"(g));
}
#define CP_COMMIT() asm volatile("cp.async.commit_group;" ::: "memory")
#define CP_WAIT(n)  asm volatile("cp.async.wait_group %0;" :: "n"(n) : "memory")

#define LDSM4(r, a) \
    asm volatile("ldmatrix.sync.aligned.m8n8.x4.shared.b16 {%0,%1,%2,%3}, [%4];" \
        : "=r"((r)[0]), "=r"((r)[1]), "=r"((r)[2]), "=r"((r)[3]) : "r"(a))
#define LDSM4T(r, a) \
    asm volatile("ldmatrix.sync.aligned.m8n8.x4.trans.shared.b16 {%0,%1,%2,%3}, [%4];" \
        : "=r"((r)[0]), "=r"((r)[1]), "=r"((r)[2]), "=r"((r)[3]) : "r"(a))

#define MMA16816(c, a, b0, b1) \
    asm volatile("mma.sync.aligned.m16n8k16.row.col.f32.f16.f16.f32 " \
        "{%0,%1,%2,%3}, {%4,%5,%6,%7}, {%8,%9}, {%0,%1,%2,%3};" \
        : "+f"((c)[0]), "+f"((c)[1]), "+f"((c)[2]), "+f"((c)[3]) \
        : "r"((a)[0]), "r"((a)[1]), "r"((a)[2]), "r"((a)[3]), "r"(b0), "r"(b1))

// -- GEMM tiling: BM=BN=128, BK=32, 3 planes/stage, 3 stages, 8 warps 2x4 ---
#define BM 128
#define BN 128
#define BK 32
#define GRS 80                             /* smem row stride bytes (40 fp16) */
#define GT  (128 * GRS)                    /* one plane tile: 10240 B */
#define GSTAGEB (3 * GT)                   /* Ah,Al,Bh: 30720 B */
#define SMEM_GEMM_BYTES (3 * GSTAGEB)      /* 92160 B */

__device__ __forceinline__ float gelu_exact(float v) {
    return 0.5f * v * (1.0f + erff(v * 0.70710678118654752f));
}

// ===== HMMA GEMM: C = (Ah+Al)[M,K] * Bh[N,K]^T (fp16 2-term split) =========
// EPI: 1 +res->fp32, 2 gelu(+bias)->planes, 3 +bias+res->fp32, 4 scale->planes
template<int EPI>
__global__ __launch_bounds__(256, 2) void hmma_gemm(
    const __half* __restrict__ Ah, const __half* __restrict__ Al,
    const __half* __restrict__ Bh,
    const float* __restrict__ bias,
    const float* __restrict__ res,
    float* __restrict__ C,
    __half* __restrict__ CH,
    __half* __restrict__ CL,
    float scale,
    int N, int K)
{
    extern __shared__ char smem[];
    const uint32_t sbase = smem_u32(smem);
    const int tid  = threadIdx.x;
    const int wid  = tid >> 5, lane = tid & 31;
    const int wm   = wid >> 2, wn = wid & 3;       // 2 x 4 warps, 64x32 tiles
    const int rowB = blockIdx.y * BM, colB = blockIdx.x * BN;

    const __half* srcs[3] = {
        Ah + (size_t)rowB * K, Al + (size_t)rowB * K, Bh + (size_t)colB * K };

    auto load_stage = [&](int s, int kt) {
        const int k0 = kt * BK;
        const uint32_t st = sbase + s * GSTAGEB;
        #pragma unroll
        for (int i = 0; i < 6; i++) {
            const int tile = i >> 1;                  // 0..2 (const per i)
            const int within = ((i & 1) << 8) + tid;  // 0..511
            const int r = within >> 2, seg = within & 3;
            cp16(st + tile * GT + r * GRS + seg * 16,
                 srcs[tile] + (size_t)r * K + k0 + seg * 8);
        }
        CP_COMMIT();
    };

    float acc[4][4][4];
    #pragma unroll
    for (int i = 0; i < 4; i++)
        #pragma unroll
        for (int j = 0; j < 4; j++)
            #pragma unroll
            for (int q = 0; q < 4; q++) acc[i][j][q] = 0.0f;

    const int niter = K / BK;
    load_stage(0, 0);
    load_stage(1, 1);

    for (int t = 0; t < niter; t++) {
        CP_WAIT(1);
        __syncthreads();
        if (t + 2 < niter) load_stage((t + 2) % 3, t + 2);

        const uint32_t st = sbase + (t % 3) * GSTAGEB;
        const uint32_t sAh = st, sAl = st + GT, sBh = st + 2*GT;

        #pragma unroll
        for (int ks = 0; ks < 2; ks++) {
            const uint32_t aoff = (wm*64 + (lane & 15)) * GRS
                                + (ks*16 + (lane >> 4) * 8) * 2;
            const uint32_t boff = (wn*32 + (lane >> 4) * 8 + (lane & 7)) * GRS
                                + (ks*16 + ((lane >> 3) & 1) * 8) * 2;
            uint32_t ah[4][4], bh[2][4];
            #pragma unroll
            for (int mi = 0; mi < 4; mi++) LDSM4(ah[mi], sAh + aoff + mi*16*GRS);
            #pragma unroll
            for (int nt = 0; nt < 2; nt++) LDSM4(bh[nt], sBh + boff + nt*16*GRS);
            #pragma unroll
            for (int mi = 0; mi < 4; mi++)
                #pragma unroll
                for (int nt = 0; nt < 2; nt++) {
                    MMA16816(acc[mi][nt*2+0], ah[mi], bh[nt][0], bh[nt][1]);
                    MMA16816(acc[mi][nt*2+1], ah[mi], bh[nt][2], bh[nt][3]);
                }
            {
                uint32_t al[4][4];
                #pragma unroll
                for (int mi = 0; mi < 4; mi++) LDSM4(al[mi], sAl + aoff + mi*16*GRS);
                #pragma unroll
                for (int mi = 0; mi < 4; mi++)
                    #pragma unroll
                    for (int nt = 0; nt < 2; nt++) {
                        MMA16816(acc[mi][nt*2+0], al[mi], bh[nt][0], bh[nt][1]);
                        MMA16816(acc[mi][nt*2+1], al[mi], bh[nt][2], bh[nt][3]);
                    }
            }
        }
        __syncthreads();
    }

    const int g  = lane >> 2;
    const int tq = lane & 3;
    #pragma unroll
    for (int mi = 0; mi < 4; mi++) {
        #pragma unroll
        for (int half = 0; half < 2; half++) {
            const int gr = rowB + wm*64 + mi*16 + g + half*8;
            #pragma unroll
            for (int ni = 0; ni < 4; ni++) {
                const int gc = colB + wn*32 + ni*8 + tq*2;
                float v0 = acc[mi][ni][half*2+0];
                float v1 = acc[mi][ni][half*2+1];
                if (EPI == 1) {
                    const float2 r2 = *reinterpret_cast<const float2*>(res + (size_t)gr * N + gc);
                    *reinterpret_cast<float2*>(C + (size_t)gr * N + gc) =
                        make_float2(v0 + r2.x, v1 + r2.y);
                } else if (EPI == 3) {
                    const float2 r2 = *reinterpret_cast<const float2*>(res + (size_t)gr * N + gc);
                    *reinterpret_cast<float2*>(C + (size_t)gr * N + gc) =
                        make_float2(v0 + bias[gc] + r2.x, v1 + bias[gc + 1] + r2.y);
                } else {
                    float s0, s1;
                    if (EPI == 2) {
                        s0 = gelu_exact(v0 + bias[gc]);
                        s1 = gelu_exact(v1 + bias[gc + 1]);
                    } else {           // EPI == 4
                        s0 = v0 * scale; s1 = v1 * scale;
                    }
                    __half2 hi2, lo2;
                    hi2.x = __float2half(s0);
                    hi2.y = __float2half(s1);
                    lo2.x = __float2half(s0 - __half2float(hi2.x));
                    lo2.y = __float2half(s1 - __half2float(hi2.y));
                    *reinterpret_cast<__half2*>(CH + (size_t)gr * N + gc) = hi2;
                    *reinterpret_cast<__half2*>(CL + (size_t)gr * N + gc) = lo2;
                }
            }
        }
    }
}

// ---------------- layernorm -> fp16 planes ---------------------------------
__global__ __launch_bounds__(256) void ln_planes(const float* __restrict__ x,
        const float* __restrict__ g, const float* __restrict__ b,
        __half* __restrict__ H, __half* __restrict__ L)
{
    __shared__ float red[256];
    const int row = blockIdx.x, t = threadIdx.x;
    const float4 v = reinterpret_cast<const float4*>(x + (size_t)row * D_MODEL)[t];
    red[t] = v.x + v.y + v.z + v.w;
    __syncthreads();
    #pragma unroll
    for (int o = 128; o > 0; o >>= 1) { if (t < o) red[t] += red[t + o]; __syncthreads(); }
    const float mu = red[0] * (1.0f / D_MODEL);
    __syncthreads();
    const float dx = v.x - mu, dy = v.y - mu, dz = v.z - mu, dw = v.w - mu;
    red[t] = dx*dx + dy*dy + dz*dz + dw*dw;
    __syncthreads();
    #pragma unroll
    for (int o = 128; o > 0; o >>= 1) { if (t < o) red[t] += red[t + o]; __syncthreads(); }
    const float rs = rsqrtf(red[0] * (1.0f / D_MODEL) + 1e-5f);
    const float4 gv = reinterpret_cast<const float4*>(g)[t];
    const float4 bv = reinterpret_cast<const float4*>(b)[t];
    float o4[4] = { dx*rs*gv.x + bv.x, dy*rs*gv.y + bv.y, dz*rs*gv.z + bv.z, dw*rs*gv.w + bv.w };
    __half h[4], l[4];
    #pragma unroll
    for (int j = 0; j < 4; j++) {
        h[j] = __float2half(o4[j]);
        l[j] = __float2half(o4[j] - __half2float(h[j]));
    }
    const size_t base = (size_t)row * D_MODEL + t * 4;
    *reinterpret_cast<uint2*>(H + base) = *reinterpret_cast<uint2*>(h);
    *reinterpret_cast<uint2*>(L + base) = *reinterpret_cast<uint2*>(l);
}

// ---------------- fp32 -> single fp16 plane (weights) ----------------------
__global__ __launch_bounds__(256) void conv_single(const float* __restrict__ src,
        __half* __restrict__ H, int total)
{
    const int i4 = blockIdx.x * 256 + threadIdx.x;
    if (i4 * 4 >= total) return;
    const float4 v = reinterpret_cast<const float4*>(src)[i4];
    __half h[4] = { __float2half(v.x), __float2half(v.y),
                    __float2half(v.z), __float2half(v.w) };
    *reinterpret_cast<uint2*>(H + (size_t)i4 * 4) = *reinterpret_cast<uint2*>(h);
}

// ========== flash attention (fp16 2-term, BQ=64, TK=64, 4 warps) ===========
#define FSTRIDE 144
#define FTILEB  (64 * FSTRIDE)         /* 9216 */
#define FQ_BYTES (2 * FTILEB)          /* qh, ql */
#define FKV_BYTES (2 * FTILEB)         /* kh, vh */
#define SMEM_FLASH_BYTES (FQ_BYTES + 2 * FKV_BYTES)  /* 55296 */

__global__ __launch_bounds__(128, 2) void flash_mma(
        const __half* __restrict__ Qh, const __half* __restrict__ Ql,
        const __half* __restrict__ Kh, const __half* __restrict__ Vh,
        __half* __restrict__ outH, __half* __restrict__ outL)
{
    extern __shared__ char smem[];
    const uint32_t sb = smem_u32(smem);
    const int tid = threadIdx.x;
    const int w = tid >> 5, lane = tid & 31;
    const int bh = blockIdx.y;                       // 0..31
    const size_t base = (size_t)(bh >> 4) * SEQ * D_MODEL + (size_t)(bh & 15) * D_HEAD;
    const int qb = blockIdx.x * 64;

    #pragma unroll
    for (int i = 0; i < 4; i++) {
        const int c = i * 128 + tid;
        const int row = c >> 3, seg = c & 7;
        const size_t goff = base + (size_t)(qb + row) * D_MODEL + seg * 8;
        cp16(sb + 0      + row * FSTRIDE + seg * 16, Qh + goff);
        cp16(sb + FTILEB + row * FSTRIDE + seg * 16, Ql + goff);
    }
    auto load_kv = [&](int buf, int kt) {
        const uint32_t kvb = sb + FQ_BYTES + buf * FKV_BYTES;
        #pragma unroll
        for (int i = 0; i < 4; i++) {
            const int c = i * 128 + tid;
            const int row = c >> 3, seg = c & 7;
            const size_t goff = base + (size_t)(kt + row) * D_MODEL + seg * 8;
            const uint32_t soff = row * FSTRIDE + seg * 16;
            cp16(kvb + 0*FTILEB + soff, Kh + goff);
            cp16(kvb + 1*FTILEB + soff, Vh + goff);
        }
        CP_COMMIT();
    };
    load_kv(0, 0);

    float m0 = -1e30f, m1 = -1e30f, l0 = 0.0f, l1 = 0.0f;
    float o[8][4];
    #pragma unroll
    for (int j = 0; j < 8; j++)
        #pragma unroll
        for (int q = 0; q < 4; q++) o[j][q] = 0.0f;

    const uint32_t aQrow = (w*16 + (lane & 15)) * FSTRIDE + (lane >> 4) * 16;
    const uint32_t bKrow = ((lane >> 4) * 8 + (lane & 7)) * FSTRIDE + ((lane >> 3) & 1) * 16;
    const uint32_t bVrow = (lane & 15) * FSTRIDE + (lane >> 4) * 16;

    uint32_t qhf[4][4], qlf[4][4];

    for (int ti = 0; ti < SEQ / 64; ti++) {
        CP_WAIT(0);
        __syncthreads();
        if (ti + 1 < SEQ / 64) load_kv((ti + 1) & 1, (ti + 1) * 64);
        if (ti == 0) {
            #pragma unroll
            for (int ks = 0; ks < 4; ks++) {
                LDSM4(qhf[ks], sb + aQrow + ks * 32);
                LDSM4(qlf[ks], sb + FTILEB + aQrow + ks * 32);
            }
        }
        const uint32_t kvb = sb + FQ_BYTES + (ti & 1) * FKV_BYTES;

        // ---- S = (qh + ql) * kh
        float s[8][4];
        #pragma unroll
        for (int j = 0; j < 8; j++)
            #pragma unroll
            for (int q = 0; q < 4; q++) s[j][q] = 0.0f;
        #pragma unroll
        for (int ks = 0; ks < 4; ks++) {
            uint32_t bkh[4][4];
            #pragma unroll
            for (int nt = 0; nt < 4; nt++)
                LDSM4(bkh[nt], kvb + bKrow + (nt*16) * FSTRIDE + ks * 32);
            #pragma unroll
            for (int nt = 0; nt < 4; nt++) {
                MMA16816(s[nt*2+0], qhf[ks], bkh[nt][0], bkh[nt][1]);
                MMA16816(s[nt*2+1], qhf[ks], bkh[nt][2], bkh[nt][3]);
            }
            #pragma unroll
            for (int nt = 0; nt < 4; nt++) {
                MMA16816(s[nt*2+0], qlf[ks], bkh[nt][0], bkh[nt][1]);
                MMA16816(s[nt*2+1], qlf[ks], bkh[nt][2], bkh[nt][3]);
            }
        }

        float mx0 = -1e30f, mx1 = -1e30f;
        #pragma unroll
        for (int j = 0; j < 8; j++) {
            mx0 = fmaxf(mx0, fmaxf(s[j][0], s[j][1]));
            mx1 = fmaxf(mx1, fmaxf(s[j][2], s[j][3]));
        }
        mx0 = fmaxf(mx0, __shfl_xor_sync(0xffffffffu, mx0, 1));
        mx0 = fmaxf(mx0, __shfl_xor_sync(0xffffffffu, mx0, 2));
        mx1 = fmaxf(mx1, __shfl_xor_sync(0xffffffffu, mx1, 1));
        mx1 = fmaxf(mx1, __shfl_xor_sync(0xffffffffu, mx1, 2));
        const float mn0 = fmaxf(m0, mx0), mn1 = fmaxf(m1, mx1);
        const float corr0 = __expf(m0 - mn0), corr1 = __expf(m1 - mn1);
        m0 = mn0; m1 = mn1;

        float sum0 = 0.0f, sum1 = 0.0f;
        uint32_t aph[16], apl[16];
        #pragma unroll
        for (int j = 0; j < 8; j++) {
            float p0 = __expf(s[j][0] - mn0), p1 = __expf(s[j][1] - mn0);
            float p2 = __expf(s[j][2] - mn1), p3 = __expf(s[j][3] - mn1);
            sum0 += p0 + p1; sum1 += p2 + p3;
            __half h0 = __float2half(p0), h1 = __float2half(p1);
            __half h2 = __float2half(p2), h3 = __float2half(p3);
            __half2 hi01 = __halves2half2(h0, h1);
            __half2 hi23 = __halves2half2(h2, h3);
            __half2 lo01 = __halves2half2(
                __float2half(p0 - __half2float(h0)),
                __float2half(p1 - __half2float(h1)));
            __half2 lo23 = __halves2half2(
                __float2half(p2 - __half2float(h2)),
                __float2half(p3 - __half2float(h3)));
            const int t4 = (j >> 1) * 4 + (j & 1) * 2;
            aph[t4 + 0] = *reinterpret_cast<uint32_t*>(&hi01);
            aph[t4 + 1] = *reinterpret_cast<uint32_t*>(&hi23);
            apl[t4 + 0] = *reinterpret_cast<uint32_t*>(&lo01);
            apl[t4 + 1] = *reinterpret_cast<uint32_t*>(&lo23);
        }
        sum0 += __shfl_xor_sync(0xffffffffu, sum0, 1);
        sum0 += __shfl_xor_sync(0xffffffffu, sum0, 2);
        sum1 += __shfl_xor_sync(0xffffffffu, sum1, 1);
        sum1 += __shfl_xor_sync(0xffffffffu, sum1, 2);
        l0 = l0 * corr0 + sum0;
        l1 = l1 * corr1 + sum1;
        #pragma unroll
        for (int j = 0; j < 8; j++) {
            o[j][0] *= corr0; o[j][1] *= corr0;
            o[j][2] *= corr1; o[j][3] *= corr1;
        }

        // ---- O += (ph + pl) * vh
        #pragma unroll
        for (int t = 0; t < 4; t++) {
            uint32_t bvh[4][4];
            #pragma unroll
            for (int ns = 0; ns < 4; ns++)
                LDSM4T(bvh[ns], kvb + FTILEB + bVrow + (t*16) * FSTRIDE + ns * 32);
            #pragma unroll
            for (int ns = 0; ns < 4; ns++) {
                MMA16816(o[ns*2+0], aph + t*4, bvh[ns][0], bvh[ns][1]);
                MMA16816(o[ns*2+1], aph + t*4, bvh[ns][2], bvh[ns][3]);
            }
            #pragma unroll
            for (int ns = 0; ns < 4; ns++) {
                MMA16816(o[ns*2+0], apl + t*4, bvh[ns][0], bvh[ns][1]);
                MMA16816(o[ns*2+1], apl + t*4, bvh[ns][2], bvh[ns][3]);
            }
        }
    }

    const float inv0 = 1.0f / l0, inv1 = 1.0f / l1;
    const int r0 = qb + w*16 + (lane >> 2);
    const int gr0 = (bh >> 4) * SEQ + r0;
    const int colb = (bh & 15) * D_HEAD + 2 * (lane & 3);
    #pragma unroll
    for (int j = 0; j < 8; j++) {
        const int col = colb + j * 8;
        float v00 = o[j][0] * inv0, v01 = o[j][1] * inv0;
        float v10 = o[j][2] * inv1, v11 = o[j][3] * inv1;
        __half2 h0, l0b, h1, l1b;
        h0.x = __float2half(v00); h0.y = __float2half(v01);
        l0b.x = __float2half(v00 - __half2float(h0.x));
        l0b.y = __float2half(v01 - __half2float(h0.y));
        h1.x = __float2half(v10); h1.y = __float2half(v11);
        l1b.x = __float2half(v10 - __half2float(h1.x));
        l1b.y = __float2half(v11 - __half2float(h1.y));
        const size_t b0 = (size_t)gr0 * D_MODEL + col;
        const size_t b1 = (size_t)(gr0 + 8) * D_MODEL + col;
        *reinterpret_cast<__half2*>(outH + b0) = h0;
        *reinterpret_cast<__half2*>(outL + b0) = l0b;
        *reinterpret_cast<__half2*>(outH + b1) = h1;
        *reinterpret_cast<__half2*>(outL + b1) = l1b;
    }
}

// ---------------- launch --------------------------------------------------
extern "C" void kernel_launch(void* const* d_in, const int* in_sizes, int n_in,
                              void* d_out, int out_size)
{
    const float* x    = (const float*)d_in[0];
    const float* wq   = (const float*)d_in[1];
    const float* wk   = (const float*)d_in[2];
    const float* wv   = (const float*)d_in[3];
    const float* wo   = (const float*)d_in[4];
    const float* w1   = (const float*)d_in[5];
    const float* b1   = (const float*)d_in[6];
    const float* w2   = (const float*)d_in[7];
    const float* b2   = (const float*)d_in[8];
    const float* ln1g = (const float*)d_in[9];
    const float* ln1b = (const float*)d_in[10];
    const float* ln2g = (const float*)d_in[11];
    const float* ln2b = (const float*)d_in[12];
    float* out = (float*)d_out;

    __half *hH,*hL,*h2H,*h2L,*atH,*atL,*ffH,*ffL;
    __half *Bq,*Bk,*Bv,*Bo,*B1,*B2;
    __half *qh,*ql,*kh,*kl,*vh,*vl;
    float *x1;
    cudaGetSymbolAddress((void**)&hH,  g_hH);   cudaGetSymbolAddress((void**)&hL,  g_hL);
    cudaGetSymbolAddress((void**)&h2H, g_h2H);  cudaGetSymbolAddress((void**)&h2L, g_h2L);
    cudaGetSymbolAddress((void**)&atH, g_atH);  cudaGetSymbolAddress((void**)&atL, g_atL);
    cudaGetSymbolAddress((void**)&ffH, g_ffH);  cudaGetSymbolAddress((void**)&ffL, g_ffL);
    cudaGetSymbolAddress((void**)&Bq,  g_Bq);   cudaGetSymbolAddress((void**)&Bk,  g_Bk);
    cudaGetSymbolAddress((void**)&Bv,  g_Bv);   cudaGetSymbolAddress((void**)&Bo,  g_Bo);
    cudaGetSymbolAddress((void**)&B1,  g_B1);   cudaGetSymbolAddress((void**)&B2,  g_B2);
    cudaGetSymbolAddress((void**)&qh,  g_qh);   cudaGetSymbolAddress((void**)&ql,  g_ql);
    cudaGetSymbolAddress((void**)&kh,  g_kh);   cudaGetSymbolAddress((void**)&kl,  g_kl);
    cudaGetSymbolAddress((void**)&vh,  g_vh);   cudaGetSymbolAddress((void**)&vl,  g_vl);
    cudaGetSymbolAddress((void**)&x1,  g_x1);

    cudaFuncSetAttribute(hmma_gemm<1>, cudaFuncAttributeMaxDynamicSharedMemorySize, SMEM_GEMM_BYTES);
    cudaFuncSetAttribute(hmma_gemm<2>, cudaFuncAttributeMaxDynamicSharedMemorySize, SMEM_GEMM_BYTES);
    cudaFuncSetAttribute(hmma_gemm<3>, cudaFuncAttributeMaxDynamicSharedMemorySize, SMEM_GEMM_BYTES);
    cudaFuncSetAttribute(hmma_gemm<4>, cudaFuncAttributeMaxDynamicSharedMemorySize, SMEM_GEMM_BYTES);
    cudaFuncSetAttribute(flash_mma,    cudaFuncAttributeMaxDynamicSharedMemorySize, SMEM_FLASH_BYTES);

    const dim3 blkG(256);
    const dim3 blk(256);
    const dim3 gP (D_MODEL/BN, NROWS/BM);    // (8, 32) = 256 CTAs
    const dim3 gF1(D_FF/BN,    NROWS/BM);    // (32, 32) = 1024 CTAs
    const dim3 gAttn(SEQ/64, BATCH*N_HEADS); // (32, 32)

    ln_planes<<<NROWS, blk>>>(x, ln1g, ln1b, hH, hL);                                        // 1
    conv_single<<<(D_MODEL*D_MODEL/4+255)/256, blk>>>(wq, Bq, D_MODEL*D_MODEL);              // 2
    conv_single<<<(D_MODEL*D_MODEL/4+255)/256, blk>>>(wk, Bk, D_MODEL*D_MODEL);              // 3
    hmma_gemm<4><<<gP, blkG, SMEM_GEMM_BYTES>>>(hH, hL, Bq, nullptr, nullptr, nullptr,
                                               qh, ql, 0.125f, D_MODEL, D_MODEL);            // 4 <- profiled
    conv_single<<<(D_MODEL*D_MODEL/4+255)/256, blk>>>(wv, Bv, D_MODEL*D_MODEL);              // 5
    hmma_gemm<4><<<gP, blkG, SMEM_GEMM_BYTES>>>(hH, hL, Bk, nullptr, nullptr, nullptr,
                                               kh, kl, 1.0f, D_MODEL, D_MODEL);              // 6
    hmma_gemm<4><<<gP, blkG, SMEM_GEMM_BYTES>>>(hH, hL, Bv, nullptr, nullptr, nullptr,
                                               vh, vl, 1.0f, D_MODEL, D_MODEL);              // 7
    conv_single<<<(D_MODEL*D_MODEL/4+255)/256, blk>>>(wo, Bo, D_MODEL*D_MODEL);              // 8
    conv_single<<<(D_FF*D_MODEL/4+255)/256,    blk>>>(w1, B1, D_FF*D_MODEL);                 // 9
    conv_single<<<(D_MODEL*D_FF/4+255)/256,    blk>>>(w2, B2, D_MODEL*D_FF);                 // 10
    flash_mma<<<gAttn, dim3(128), SMEM_FLASH_BYTES>>>(qh, ql, kh, vh, atH, atL);             // 11
    hmma_gemm<1><<<gP, blkG, SMEM_GEMM_BYTES>>>(atH, atL, Bo, nullptr, x, x1,
                                               nullptr, nullptr, 1.0f, D_MODEL, D_MODEL);    // 12
    ln_planes<<<NROWS, blk>>>(x1, ln2g, ln2b, h2H, h2L);                                     // 13
    hmma_gemm<2><<<gF1, blkG, SMEM_GEMM_BYTES>>>(h2H, h2L, B1, b1, nullptr, nullptr,
                                               ffH, ffL, 1.0f, D_FF, D_MODEL);               // 14
    hmma_gemm<3><<<gP, blkG, SMEM_GEMM_BYTES>>>(ffH, ffL, B2, b2, x1, out,
                                               nullptr, nullptr, 1.0f, D_MODEL, D_FF);       // 15
}

// round 12
// speedup vs baseline: 2.1787x; 1.5999x over previous
#include <cuda_runtime.h>
#include <cuda_fp16.h>
#include <math.h>
#include <cstdint>

#define D_MODEL 1024
#define D_FF    4096
#define N_HEADS 16
#define D_HEAD  64
#define BATCH   2
#define SEQ     2048
#define NROWS   (BATCH*SEQ)   /* 4096 */

// ---------------- scratch (device globals; no allocation allowed) ----------
__device__ __half g_h   [NROWS * D_MODEL];
__device__ __half g_h2  [NROWS * D_MODEL];
__device__ __half g_at  [NROWS * D_MODEL];
__device__ __half g_ff  [NROWS * D_FF];
__device__ __half g_Bq  [D_MODEL * D_MODEL];
__device__ __half g_Bk  [D_MODEL * D_MODEL];
__device__ __half g_Bv  [D_MODEL * D_MODEL];
__device__ __half g_Bo  [D_MODEL * D_MODEL];
__device__ __half g_B1  [D_FF * D_MODEL];
__device__ __half g_B2  [D_MODEL * D_FF];
__device__ __half g_q   [NROWS * D_MODEL];
__device__ __half g_k   [NROWS * D_MODEL];
__device__ __half g_v   [NROWS * D_MODEL];
__device__ float  g_x1  [NROWS * D_MODEL];

// ================= PTX helpers =============================================
__device__ __forceinline__ uint32_t smem_u32(const void* p) {
    uint32_t a;
    asm("{ .reg .u64 t; cvta.to.shared.u64 t, %1; cvt.u32.u64 %0, t; }" : "=r"(a) : "l"(p));
    return a;
}
__device__ __forceinline__ void cp16(uint32_t s, const void* g) {
    asm volatile("cp.async.cg.shared.global [%0], [%1], 16;" :: "r"(s), "l"(g));
}
#define CP_COMMIT() asm volatile("cp.async.commit_group;" ::: "memory")
#define CP_WAIT(n)  asm volatile("cp.async.wait_group %0;" :: "n"(n) : "memory")

#define LDSM4(r, a) \
    asm volatile("ldmatrix.sync.aligned.m8n8.x4.shared.b16 {%0,%1,%2,%3}, [%4];" \
        : "=r"((r)[0]), "=r"((r)[1]), "=r"((r)[2]), "=r"((r)[3]) : "r"(a))
#define LDSM4T(r, a) \
    asm volatile("ldmatrix.sync.aligned.m8n8.x4.trans.shared.b16 {%0,%1,%2,%3}, [%4];" \
        : "=r"((r)[0]), "=r"((r)[1]), "=r"((r)[2]), "=r"((r)[3]) : "r"(a))

#define MMA16816(c, a, b0, b1) \
    asm volatile("mma.sync.aligned.m16n8k16.row.col.f32.f16.f16.f32 " \
        "{%0,%1,%2,%3}, {%4,%5,%6,%7}, {%8,%9}, {%0,%1,%2,%3};" \
        : "+f"((c)[0]), "+f"((c)[1]), "+f"((c)[2]), "+f"((c)[3]) \
        : "r"((a)[0]), "r"((a)[1]), "r"((a)[2]), "r"((a)[3]), "r"(b0), "r"(b1))

// -- GEMM tiling: BM=BN=128, BK=32, 2 planes/stage, 3 stages, 8 warps 2x4 ---
#define BM 128
#define BN 128
#define BK 32
#define GRS 80                             /* smem row stride bytes (40 fp16) */
#define GT  (128 * GRS)                    /* one tile: 10240 B */
#define GSTAGEB (2 * GT)                   /* A,B: 20480 B */
#define SMEM_GEMM_BYTES (3 * GSTAGEB)      /* 61440 B */

__device__ __forceinline__ float gelu_exact(float v) {
    return 0.5f * v * (1.0f + erff(v * 0.70710678118654752f));
}

// ===== HMMA GEMM: C[M,N] = A[M,K] * B[N,K]^T  (fp16 in, fp32 accum) ========
// EPI: 1 +res->fp32, 2 gelu(+bias)->fp16, 3 +bias+res->fp32, 4 scale->fp16
template<int EPI>
__global__ __launch_bounds__(256, 2) void hmma_gemm(
    const __half* __restrict__ A,
    const __half* __restrict__ B,
    const float* __restrict__ bias,
    const float* __restrict__ res,
    float* __restrict__ C,
    __half* __restrict__ CH,
    float scale,
    int N, int K)
{
    extern __shared__ char smem[];
    const uint32_t sbase = smem_u32(smem);
    const int tid  = threadIdx.x;
    const int wid  = tid >> 5, lane = tid & 31;
    const int wm   = wid >> 2, wn = wid & 3;       // 2 x 4 warps, 64x32 tiles
    const int rowB = blockIdx.y * BM, colB = blockIdx.x * BN;

    const __half* srcs[2] = { A + (size_t)rowB * K, B + (size_t)colB * K };

    auto load_stage = [&](int s, int kt) {
        const int k0 = kt * BK;
        const uint32_t st = sbase + s * GSTAGEB;
        #pragma unroll
        for (int i = 0; i < 4; i++) {
            const int tile = i >> 1;                  // 0..1
            const int within = ((i & 1) << 8) + tid;  // 0..511
            const int r = within >> 2, seg = within & 3;
            cp16(st + tile * GT + r * GRS + seg * 16,
                 srcs[tile] + (size_t)r * K + k0 + seg * 8);
        }
        CP_COMMIT();
    };

    float acc[4][4][4];
    #pragma unroll
    for (int i = 0; i < 4; i++)
        #pragma unroll
        for (int j = 0; j < 4; j++)
            #pragma unroll
            for (int q = 0; q < 4; q++) acc[i][j][q] = 0.0f;

    const int niter = K / BK;
    load_stage(0, 0);
    load_stage(1, 1);

    for (int t = 0; t < niter; t++) {
        CP_WAIT(1);
        __syncthreads();
        if (t + 2 < niter) load_stage((t + 2) % 3, t + 2);

        const uint32_t st = sbase + (t % 3) * GSTAGEB;
        const uint32_t sA = st, sB = st + GT;

        #pragma unroll
        for (int ks = 0; ks < 2; ks++) {
            const uint32_t aoff = (wm*64 + (lane & 15)) * GRS
                                + (ks*16 + (lane >> 4) * 8) * 2;
            const uint32_t boff = (wn*32 + (lane >> 4) * 8 + (lane & 7)) * GRS
                                + (ks*16 + ((lane >> 3) & 1) * 8) * 2;
            uint32_t a[4][4], b[2][4];
            #pragma unroll
            for (int mi = 0; mi < 4; mi++) LDSM4(a[mi], sA + aoff + mi*16*GRS);
            #pragma unroll
            for (int nt = 0; nt < 2; nt++) LDSM4(b[nt], sB + boff + nt*16*GRS);
            #pragma unroll
            for (int mi = 0; mi < 4; mi++)
                #pragma unroll
                for (int nt = 0; nt < 2; nt++) {
                    MMA16816(acc[mi][nt*2+0], a[mi], b[nt][0], b[nt][1]);
                    MMA16816(acc[mi][nt*2+1], a[mi], b[nt][2], b[nt][3]);
                }
        }
        __syncthreads();
    }

    const int g  = lane >> 2;
    const int tq = lane & 3;
    #pragma unroll
    for (int mi = 0; mi < 4; mi++) {
        #pragma unroll
        for (int half = 0; half < 2; half++) {
            const int gr = rowB + wm*64 + mi*16 + g + half*8;
            #pragma unroll
            for (int ni = 0; ni < 4; ni++) {
                const int gc = colB + wn*32 + ni*8 + tq*2;
                float v0 = acc[mi][ni][half*2+0];
                float v1 = acc[mi][ni][half*2+1];
                if (EPI == 1) {
                    const float2 r2 = *reinterpret_cast<const float2*>(res + (size_t)gr * N + gc);
                    *reinterpret_cast<float2*>(C + (size_t)gr * N + gc) =
                        make_float2(v0 + r2.x, v1 + r2.y);
                } else if (EPI == 3) {
                    const float2 r2 = *reinterpret_cast<const float2*>(res + (size_t)gr * N + gc);
                    *reinterpret_cast<float2*>(C + (size_t)gr * N + gc) =
                        make_float2(v0 + bias[gc] + r2.x, v1 + bias[gc + 1] + r2.y);
                } else {
                    float s0, s1;
                    if (EPI == 2) {
                        s0 = gelu_exact(v0 + bias[gc]);
                        s1 = gelu_exact(v1 + bias[gc + 1]);
                    } else {           // EPI == 4
                        s0 = v0 * scale; s1 = v1 * scale;
                    }
                    __half2 h2v;
                    h2v.x = __float2half(s0);
                    h2v.y = __float2half(s1);
                    *reinterpret_cast<__half2*>(CH + (size_t)gr * N + gc) = h2v;
                }
            }
        }
    }
}

// ---------------- layernorm -> fp16 ----------------------------------------
__global__ __launch_bounds__(256) void ln_half(const float* __restrict__ x,
        const float* __restrict__ g, const float* __restrict__ b,
        __half* __restrict__ H)
{
    __shared__ float red[256];
    const int row = blockIdx.x, t = threadIdx.x;
    const float4 v = reinterpret_cast<const float4*>(x + (size_t)row * D_MODEL)[t];
    red[t] = v.x + v.y + v.z + v.w;
    __syncthreads();
    #pragma unroll
    for (int o = 128; o > 0; o >>= 1) { if (t < o) red[t] += red[t + o]; __syncthreads(); }
    const float mu = red[0] * (1.0f / D_MODEL);
    __syncthreads();
    const float dx = v.x - mu, dy = v.y - mu, dz = v.z - mu, dw = v.w - mu;
    red[t] = dx*dx + dy*dy + dz*dz + dw*dw;
    __syncthreads();
    #pragma unroll
    for (int o = 128; o > 0; o >>= 1) { if (t < o) red[t] += red[t + o]; __syncthreads(); }
    const float rs = rsqrtf(red[0] * (1.0f / D_MODEL) + 1e-5f);
    const float4 gv = reinterpret_cast<const float4*>(g)[t];
    const float4 bv = reinterpret_cast<const float4*>(b)[t];
    __half h[4] = {
        __float2half(dx*rs*gv.x + bv.x), __float2half(dy*rs*gv.y + bv.y),
        __float2half(dz*rs*gv.z + bv.z), __float2half(dw*rs*gv.w + bv.w) };
    *reinterpret_cast<uint2*>(H + (size_t)row * D_MODEL + t * 4) =
        *reinterpret_cast<uint2*>(h);
}

// ---------------- fp32 -> fp16 (weights) -----------------------------------
__global__ __launch_bounds__(256) void conv_single(const float* __restrict__ src,
        __half* __restrict__ H, int total)
{
    const int i4 = blockIdx.x * 256 + threadIdx.x;
    if (i4 * 4 >= total) return;
    const float4 v = reinterpret_cast<const float4*>(src)[i4];
    __half h[4] = { __float2half(v.x), __float2half(v.y),
                    __float2half(v.z), __float2half(v.w) };
    *reinterpret_cast<uint2*>(H + (size_t)i4 * 4) = *reinterpret_cast<uint2*>(h);
}

// ========== flash attention (fp16, BQ=64, TK=64, 4 warps) ==================
#define FSTRIDE 144
#define FTILEB  (64 * FSTRIDE)         /* 9216 */
#define FQ_BYTES (FTILEB)              /* q */
#define FKV_BYTES (2 * FTILEB)         /* k, v */
#define SMEM_FLASH_BYTES (FQ_BYTES + 2 * FKV_BYTES)  /* 46080 */

__global__ __launch_bounds__(128, 2) void flash_mma(
        const __half* __restrict__ Q,
        const __half* __restrict__ Kh, const __half* __restrict__ Vh,
        __half* __restrict__ outH)
{
    extern __shared__ char smem[];
    const uint32_t sb = smem_u32(smem);
    const int tid = threadIdx.x;
    const int w = tid >> 5, lane = tid & 31;
    const int bh = blockIdx.y;                       // 0..31
    const size_t base = (size_t)(bh >> 4) * SEQ * D_MODEL + (size_t)(bh & 15) * D_HEAD;
    const int qb = blockIdx.x * 64;

    #pragma unroll
    for (int i = 0; i < 4; i++) {
        const int c = i * 128 + tid;
        const int row = c >> 3, seg = c & 7;
        const size_t goff = base + (size_t)(qb + row) * D_MODEL + seg * 8;
        cp16(sb + row * FSTRIDE + seg * 16, Q + goff);
    }
    auto load_kv = [&](int buf, int kt) {
        const uint32_t kvb = sb + FQ_BYTES + buf * FKV_BYTES;
        #pragma unroll
        for (int i = 0; i < 4; i++) {
            const int c = i * 128 + tid;
            const int row = c >> 3, seg = c & 7;
            const size_t goff = base + (size_t)(kt + row) * D_MODEL + seg * 8;
            const uint32_t soff = row * FSTRIDE + seg * 16;
            cp16(kvb + 0*FTILEB + soff, Kh + goff);
            cp16(kvb + 1*FTILEB + soff, Vh + goff);
        }
        CP_COMMIT();
    };
    load_kv(0, 0);

    float m0 = -1e30f, m1 = -1e30f, l0 = 0.0f, l1 = 0.0f;
    float o[8][4];
    #pragma unroll
    for (int j = 0; j < 8; j++)
        #pragma unroll
        for (int q = 0; q < 4; q++) o[j][q] = 0.0f;

    const uint32_t aQrow = (w*16 + (lane & 15)) * FSTRIDE + (lane >> 4) * 16;
    const uint32_t bKrow = ((lane >> 4) * 8 + (lane & 7)) * FSTRIDE + ((lane >> 3) & 1) * 16;
    const uint32_t bVrow = (lane & 15) * FSTRIDE + (lane >> 4) * 16;

    uint32_t qf[4][4];

    for (int ti = 0; ti < SEQ / 64; ti++) {
        CP_WAIT(0);
        __syncthreads();
        if (ti + 1 < SEQ / 64) load_kv((ti + 1) & 1, (ti + 1) * 64);
        if (ti == 0) {
            #pragma unroll
            for (int ks = 0; ks < 4; ks++) LDSM4(qf[ks], sb + aQrow + ks * 32);
        }
        const uint32_t kvb = sb + FQ_BYTES + (ti & 1) * FKV_BYTES;

        // ---- S = q * k
        float s[8][4];
        #pragma unroll
        for (int j = 0; j < 8; j++)
            #pragma unroll
            for (int q = 0; q < 4; q++) s[j][q] = 0.0f;
        #pragma unroll
        for (int ks = 0; ks < 4; ks++) {
            uint32_t bkh[4][4];
            #pragma unroll
            for (int nt = 0; nt < 4; nt++)
                LDSM4(bkh[nt], kvb + bKrow + (nt*16) * FSTRIDE + ks * 32);
            #pragma unroll
            for (int nt = 0; nt < 4; nt++) {
                MMA16816(s[nt*2+0], qf[ks], bkh[nt][0], bkh[nt][1]);
                MMA16816(s[nt*2+1], qf[ks], bkh[nt][2], bkh[nt][3]);
            }
        }

        float mx0 = -1e30f, mx1 = -1e30f;
        #pragma unroll
        for (int j = 0; j < 8; j++) {
            mx0 = fmaxf(mx0, fmaxf(s[j][0], s[j][1]));
            mx1 = fmaxf(mx1, fmaxf(s[j][2], s[j][3]));
        }
        mx0 = fmaxf(mx0, __shfl_xor_sync(0xffffffffu, mx0, 1));
        mx0 = fmaxf(mx0, __shfl_xor_sync(0xffffffffu, mx0, 2));
        mx1 = fmaxf(mx1, __shfl_xor_sync(0xffffffffu, mx1, 1));
        mx1 = fmaxf(mx1, __shfl_xor_sync(0xffffffffu, mx1, 2));
        const float mn0 = fmaxf(m0, mx0), mn1 = fmaxf(m1, mx1);
        const float corr0 = __expf(m0 - mn0), corr1 = __expf(m1 - mn1);
        m0 = mn0; m1 = mn1;

        float sum0 = 0.0f, sum1 = 0.0f;
        uint32_t ap[16];
        #pragma unroll
        for (int j = 0; j < 8; j++) {
            float p0 = __expf(s[j][0] - mn0), p1 = __expf(s[j][1] - mn0);
            float p2 = __expf(s[j][2] - mn1), p3 = __expf(s[j][3] - mn1);
            sum0 += p0 + p1; sum1 += p2 + p3;
            __half2 hi01 = __halves2half2(__float2half(p0), __float2half(p1));
            __half2 hi23 = __halves2half2(__float2half(p2), __float2half(p3));
            const int t4 = (j >> 1) * 4 + (j & 1) * 2;
            ap[t4 + 0] = *reinterpret_cast<uint32_t*>(&hi01);
            ap[t4 + 1] = *reinterpret_cast<uint32_t*>(&hi23);
        }
        sum0 += __shfl_xor_sync(0xffffffffu, sum0, 1);
        sum0 += __shfl_xor_sync(0xffffffffu, sum0, 2);
        sum1 += __shfl_xor_sync(0xffffffffu, sum1, 1);
        sum1 += __shfl_xor_sync(0xffffffffu, sum1, 2);
        l0 = l0 * corr0 + sum0;
        l1 = l1 * corr1 + sum1;
        #pragma unroll
        for (int j = 0; j < 8; j++) {
            o[j][0] *= corr0; o[j][1] *= corr0;
            o[j][2] *= corr1; o[j][3] *= corr1;
        }

        // ---- O += p * v
        #pragma unroll
        for (int t = 0; t < 4; t++) {
            uint32_t bvh[4][4];
            #pragma unroll
            for (int ns = 0; ns < 4; ns++)
                LDSM4T(bvh[ns], kvb + FTILEB + bVrow + (t*16) * FSTRIDE + ns * 32);
            #pragma unroll
            for (int ns = 0; ns < 4; ns++) {
                MMA16816(o[ns*2+0], ap + t*4, bvh[ns][0], bvh[ns][1]);
                MMA16816(o[ns*2+1], ap + t*4, bvh[ns][2], bvh[ns][3]);
            }
        }
    }

    const float inv0 = 1.0f / l0, inv1 = 1.0f / l1;
    const int r0 = qb + w*16 + (lane >> 2);
    const int gr0 = (bh >> 4) * SEQ + r0;
    const int colb = (bh & 15) * D_HEAD + 2 * (lane & 3);
    #pragma unroll
    for (int j = 0; j < 8; j++) {
        const int col = colb + j * 8;
        __half2 h0, h1;
        h0.x = __float2half(o[j][0] * inv0);
        h0.y = __float2half(o[j][1] * inv0);
        h1.x = __float2half(o[j][2] * inv1);
        h1.y = __float2half(o[j][3] * inv1);
        *reinterpret_cast<__half2*>(outH + (size_t)gr0 * D_MODEL + col) = h0;
        *reinterpret_cast<__half2*>(outH + (size_t)(gr0 + 8) * D_MODEL + col) = h1;
    }
}

// ---------------- launch --------------------------------------------------
extern "C" void kernel_launch(void* const* d_in, const int* in_sizes, int n_in,
                              void* d_out, int out_size)
{
    const float* x    = (const float*)d_in[0];
    const float* wq   = (const float*)d_in[1];
    const float* wk   = (const float*)d_in[2];
    const float* wv   = (const float*)d_in[3];
    const float* wo   = (const float*)d_in[4];
    const float* w1   = (const float*)d_in[5];
    const float* b1   = (const float*)d_in[6];
    const float* w2   = (const float*)d_in[7];
    const float* b2   = (const float*)d_in[8];
    const float* ln1g = (const float*)d_in[9];
    const float* ln1b = (const float*)d_in[10];
    const float* ln2g = (const float*)d_in[11];
    const float* ln2b = (const float*)d_in[12];
    float* out = (float*)d_out;

    __half *h, *h2, *at, *ff, *Bq, *Bk, *Bv, *Bo, *B1, *B2, *q, *k, *v;
    float *x1;
    cudaGetSymbolAddress((void**)&h,   g_h);
    cudaGetSymbolAddress((void**)&h2,  g_h2);
    cudaGetSymbolAddress((void**)&at,  g_at);
    cudaGetSymbolAddress((void**)&ff,  g_ff);
    cudaGetSymbolAddress((void**)&Bq,  g_Bq);   cudaGetSymbolAddress((void**)&Bk,  g_Bk);
    cudaGetSymbolAddress((void**)&Bv,  g_Bv);   cudaGetSymbolAddress((void**)&Bo,  g_Bo);
    cudaGetSymbolAddress((void**)&B1,  g_B1);   cudaGetSymbolAddress((void**)&B2,  g_B2);
    cudaGetSymbolAddress((void**)&q,   g_q);
    cudaGetSymbolAddress((void**)&k,   g_k);
    cudaGetSymbolAddress((void**)&v,   g_v);
    cudaGetSymbolAddress((void**)&x1,  g_x1);

    cudaFuncSetAttribute(hmma_gemm<1>, cudaFuncAttributeMaxDynamicSharedMemorySize, SMEM_GEMM_BYTES);
    cudaFuncSetAttribute(hmma_gemm<2>, cudaFuncAttributeMaxDynamicSharedMemorySize, SMEM_GEMM_BYTES);
    cudaFuncSetAttribute(hmma_gemm<3>, cudaFuncAttributeMaxDynamicSharedMemorySize, SMEM_GEMM_BYTES);
    cudaFuncSetAttribute(hmma_gemm<4>, cudaFuncAttributeMaxDynamicSharedMemorySize, SMEM_GEMM_BYTES);
    cudaFuncSetAttribute(flash_mma,    cudaFuncAttributeMaxDynamicSharedMemorySize, SMEM_FLASH_BYTES);

    const dim3 blkG(256);
    const dim3 blk(256);
    const dim3 gP (D_MODEL/BN, NROWS/BM);    // (8, 32) = 256 CTAs
    const dim3 gF1(D_FF/BN,    NROWS/BM);    // (32, 32) = 1024 CTAs
    const dim3 gAttn(SEQ/64, BATCH*N_HEADS); // (32, 32)

    ln_half<<<NROWS, blk>>>(x, ln1g, ln1b, h);                                       // 1
    conv_single<<<(D_MODEL*D_MODEL/4+255)/256, blk>>>(wq, Bq, D_MODEL*D_MODEL);      // 2
    conv_single<<<(D_MODEL*D_MODEL/4+255)/256, blk>>>(wk, Bk, D_MODEL*D_MODEL);      // 3
    hmma_gemm<4><<<gP, blkG, SMEM_GEMM_BYTES>>>(h, Bq, nullptr, nullptr, nullptr,
                                               q, 0.125f, D_MODEL, D_MODEL);         // 4 <- profiled
    conv_single<<<(D_MODEL*D_MODEL/4+255)/256, blk>>>(wv, Bv, D_MODEL*D_MODEL);      // 5
    hmma_gemm<4><<<gP, blkG, SMEM_GEMM_BYTES>>>(h, Bk, nullptr, nullptr, nullptr,
                                               k, 1.0f, D_MODEL, D_MODEL);           // 6
    hmma_gemm<4><<<gP, blkG, SMEM_GEMM_BYTES>>>(h, Bv, nullptr, nullptr, nullptr,
                                               v, 1.0f, D_MODEL, D_MODEL);           // 7
    conv_single<<<(D_MODEL*D_MODEL/4+255)/256, blk>>>(wo, Bo, D_MODEL*D_MODEL);      // 8
    conv_single<<<(D_FF*D_MODEL/4+255)/256,    blk>>>(w1, B1, D_FF*D_MODEL);         // 9
    conv_single<<<(D_MODEL*D_FF/4+255)/256,    blk>>>(w2, B2, D_MODEL*D_FF);         // 10
    flash_mma<<<gAttn, dim3(128), SMEM_FLASH_BYTES>>>(q, k, v, at);                  // 11
    hmma_gemm<1><<<gP, blkG, SMEM_GEMM_BYTES>>>(at, Bo, nullptr, x, x1,
                                               nullptr, 1.0f, D_MODEL, D_MODEL);     // 12
    ln_half<<<NROWS, blk>>>(x1, ln2g, ln2b, h2);                                     // 13
    hmma_gemm<2><<<gF1, blkG, SMEM_GEMM_BYTES>>>(h2, B1, b1, nullptr, nullptr,
                                               ff, 1.0f, D_FF, D_MODEL);             // 14
    hmma_gemm<3><<<gP, blkG, SMEM_GEMM_BYTES>>>(ff, B2, b2, x1, out,
                                               nullptr, 1.0f, D_MODEL, D_FF);        // 15
}